// round 15
// baseline (speedup 1.0000x reference)
#include <cuda_runtime.h>

#define NTOK 512
#define DSTATE 192
#define HID 512
#define EMB 1024
#define NEMB 32
#define KC 256   // K rows per consumer block (HID / 2 k-halves)
#define CHT 24   // tokens per chunk (P <= 12 pairs)
#define HSS 28   // smem row stride (floats): 112 B rows, 16B-aligned

#define N_PROD 512   // producer blocks: (e,m,jq)
#define N_CONS 1024  // consumer blocks: (e,m,kh,tile)

// scratch (allocs forbidden -> device globals)
__device__ int g_start[NEMB + 1];
__device__ int g_tokens[NTOK];
__device__ float g_H[NTOK * 4 * HID];  // [slot][m][HID]
__device__ int g_flags[N_PROD + 1];    // [ (m*32+e)*4 + jq ], last = publish flag

struct Params {
    const float* W1[4];
    const float* b1[4];
    const float* W2[4];
    const float* b2[4];
    const float* te[4];
};

__device__ __forceinline__ void fma2(unsigned long long& acc,
                                     unsigned long long h2,
                                     unsigned long long w2) {
    asm("fma.rn.f32x2 %0, %1, %2, %0;" : "+l"(acc) : "l"(h2), "l"(w2));
}
__device__ __forceinline__ unsigned long long splat2(float v) {
    unsigned long long r;
    asm("mov.b64 %0, {%1,%1};" : "=l"(r) : "r"(__float_as_uint(v)));
    return r;
}

// ---------------------------------------------------------------------------
// Producer: grouping + H for 128 hidden columns of (e,m).
// ---------------------------------------------------------------------------
template <int L, int OFF>
__device__ __forceinline__ void prod_mlp(const float* __restrict__ state,
                                         const float* __restrict__ W1,
                                         float b, int m, int j, int s0, int n,
                                         const int* __restrict__ s_tokens,
                                         float* __restrict__ xs) {
    int tid = threadIdx.x; // 128
    #pragma unroll 1
    for (int cb = 0; cb < n; cb += 16) {
        int rem = min(n - cb, 16);
        __syncthreads();
        #pragma unroll 1
        for (int idx = tid; idx < 16 * L; idx += 128) {
            int tk = idx / L, l = idx - tk * L;
            float v = 0.f;
            if (tk < rem) {
                int tok = s_tokens[s0 + cb + tk];
                v = state[tok * DSTATE + OFF + l];
            }
            xs[tk * L + l] = v;
        }
        __syncthreads();

        float acc[16];
        #pragma unroll
        for (int t = 0; t < 16; t++) acc[t] = b;

        #pragma unroll 1
        for (int l0 = 0; l0 < L; l0 += 8) {
            float w[8];
            #pragma unroll
            for (int u = 0; u < 8; u++)
                w[u] = W1[(l0 + u) * HID + j];
            #pragma unroll
            for (int u = 0; u < 8; u++) {
                #pragma unroll
                for (int t = 0; t < 16; t++)
                    acc[t] = fmaf(xs[t * L + l0 + u], w[u], acc[t]);
            }
        }

        #pragma unroll
        for (int t = 0; t < 16; t++) {
            if (t < rem)
                g_H[((size_t)(s0 + cb + t) * 4 + m) * HID + j] = fmaxf(acc[t], 0.f);
        }
        __syncthreads();
    }
}

__device__ __forceinline__ void producer(const Params& p,
                                         const float* __restrict__ state,
                                         const int* __restrict__ ids_raw,
                                         int bid, char* smem_raw) {
    int tid  = threadIdx.x; // 128
    int warp = tid >> 5, lane = tid & 31;

    int*   s_wcnt   = (int*)smem_raw;          // 512
    int*   s_woff   = s_wcnt + 512;            // 512
    int*   s_start  = s_woff + 512;            // 33
    int*   s_tokens = s_start + 33;            // 512
    float* xs       = (float*)(s_tokens + 512);// 16*64
    __shared__ int s_i64;

    for (int i = tid; i < 512; i += 128) s_wcnt[i] = 0;
    if (tid == 0) s_i64 = 1;
    __syncthreads();
    // int64 ids (<32) have zero high words at odd int32 indices (first 512
    // words only -> in-bounds for int32 buffers too).
    if (ids_raw[2 * tid + 1] != 0) s_i64 = 0;                 // t = tid  (<256)
    if (ids_raw[2 * (tid + 128) + 1] != 0) s_i64 = 0;         // t = tid+128
    __syncthreads();

    int cs[4], rk[4];
    #pragma unroll
    for (int r = 0; r < 4; r++) {
        int t = tid + 128 * r;
        int c = s_i64 ? ids_raw[2 * t] : ids_raw[t];
        cs[r] = c;
        unsigned same = __match_any_sync(0xffffffffu, c);
        rk[r] = __popc(same & ((1u << lane) - 1u));
        if (rk[r] == 0) s_wcnt[(r * 4 + warp) * NEMB + c] = __popc(same);
    }
    __syncthreads();

    if (tid < NEMB) {
        int sum = 0;
        #pragma unroll
        for (int w = 0; w < 16; w++) {
            int c = s_wcnt[w * NEMB + tid];
            s_woff[w * NEMB + tid] = sum;
            sum += c;
        }
        s_wcnt[tid] = sum; // total per id
    }
    __syncthreads();
    if (tid <= NEMB) {
        int s = 0;
        for (int jj = 0; jj < tid && jj < NEMB; jj++) s += s_wcnt[jj];
        s_start[tid] = s;
    }
    __syncthreads();

    #pragma unroll
    for (int r = 0; r < 4; r++) {
        int slot = s_start[cs[r]] + s_woff[(r * 4 + warp) * NEMB + cs[r]] + rk[r];
        s_tokens[slot] = tid + 128 * r;
    }
    __syncthreads();

    // decode (e,m,jq):  bid = e*16 + m*4 + jq
    int jq = bid & 3;
    int m  = (bid >> 2) & 3;
    int e  = bid >> 4;

    if (bid == 0) {
        if (tid <= NEMB) g_start[tid] = s_start[tid];
        for (int i = tid; i < NTOK; i += 128) g_tokens[i] = s_tokens[i];
        __threadfence();
        __syncthreads();
        if (tid == 0) *(volatile int*)&g_flags[N_PROD] = 1;
    }

    int s0 = s_start[e];
    int n  = s_start[e + 1] - s0;
    int j  = jq * 128 + tid;

    if (n > 0) {
        float b;
        switch (m) {
            case 0: b = p.b1[0][e * HID + j];
                    prod_mlp<64, 0  >(state, p.W1[0] + (size_t)e * 64 * HID, b, 0, j, s0, n, s_tokens, xs); break;
            case 1: b = p.b1[1][e * HID + j];
                    prod_mlp<64, 64 >(state, p.W1[1] + (size_t)e * 64 * HID, b, 1, j, s0, n, s_tokens, xs); break;
            case 2: b = p.b1[2][e * HID + j];
                    prod_mlp<32, 128>(state, p.W1[2] + (size_t)e * 32 * HID, b, 2, j, s0, n, s_tokens, xs); break;
            case 3: b = p.b1[3][e * HID + j];
                    prod_mlp<32, 160>(state, p.W1[3] + (size_t)e * 32 * HID, b, 3, j, s0, n, s_tokens, xs); break;
        }
    }
    __threadfence();
    __syncthreads();
    if (tid == 0)
        *(volatile int*)&g_flags[(m * 32 + e) * 4 + jq] = 1;
}

// ---------------------------------------------------------------------------
// Consumer: K-split W2 stream + atomic epilogue (byte-identical R14 body).
// ---------------------------------------------------------------------------
#define WD 8  // W2 prefetch group size (LDG.64 each -> 16 lines/warp)

template <int P>
__device__ __forceinline__ void consume(const float2* w, const float* hs, int g,
                                        unsigned long long* a0, unsigned long long* a1) {
    #pragma unroll
    for (int j = 0; j < WD; j++) {
        unsigned long long w0 = splat2(w[j].x);
        unsigned long long w1 = splat2(w[j].y);
        const float* hrow = hs + (g + j) * HSS;
        #pragma unroll
        for (int p2 = 0; p2 < P / 2; p2++) {
            ulonglong2 hv = *(const ulonglong2*)(hrow + 4 * p2); // LDS.128 bcast
            fma2(a0[2 * p2],     hv.x, w0);
            fma2(a0[2 * p2 + 1], hv.y, w0);
            fma2(a1[2 * p2],     hv.x, w1);
            fma2(a1[2 * p2 + 1], hv.y, w1);
        }
    }
}

template <int P>  // P even, 2..12: token pairs in flight
__device__ __forceinline__ void run_chunk(
    float* hs, const float* __restrict__ W2ec, const float* __restrict__ Hme,
    float2 init, int s0cb, int rem, int tid, int c0, int m,
    float* __restrict__ out)
{
    unsigned long long a0[P], a1[P];
    unsigned long long i0 = splat2(init.x), i1 = splat2(init.y);
    #pragma unroll
    for (int p = 0; p < P; p++) { a0[p] = i0; a1[p] = i1; }

    __syncthreads();
    #pragma unroll
    for (int tk = 0; tk < 2 * P; tk++) {
        int slot = min(s0cb + tk, NTOK - 1); // clamp pad (discarded later)
        const float* src = Hme + (size_t)slot * (4 * HID);
        #pragma unroll
        for (int kk = 0; kk < KC; kk += 128)
            hs[(kk + tid) * HSS + tk] = src[kk + tid];
    }
    __syncthreads();

    float2 wA[WD], wB[WD];
    #pragma unroll
    for (int j = 0; j < WD; j++)
        wA[j] = __ldcs((const float2*)(W2ec + (size_t)j * EMB));

    #pragma unroll 1
    for (int g = 0; g < KC - 2 * WD; g += 2 * WD) {
        #pragma unroll
        for (int j = 0; j < WD; j++)
            wB[j] = __ldcs((const float2*)(W2ec + (size_t)(g + WD + j) * EMB));
        consume<P>(wA, hs, g, a0, a1);
        #pragma unroll
        for (int j = 0; j < WD; j++)
            wA[j] = __ldcs((const float2*)(W2ec + (size_t)(g + 2 * WD + j) * EMB));
        consume<P>(wB, hs, g + WD, a0, a1);
    }
    #pragma unroll
    for (int j = 0; j < WD; j++)
        wB[j] = __ldcs((const float2*)(W2ec + (size_t)(KC - WD + j) * EMB));
    consume<P>(wA, hs, KC - 2 * WD, a0, a1);
    consume<P>(wB, hs, KC - WD, a0, a1);

    // atomic epilogue: out memset to 0; exactly two commutative adds/element
    #pragma unroll
    for (int p = 0; p < P; p++) {
        float2 vA = *(float2*)&a0[p];
        float2 vB = *(float2*)&a1[p];
        int t0 = 2 * p;
        if (t0 < rem) {
            int tok = g_tokens[s0cb + t0];
            float* dst = &out[((size_t)tok * 4 + m) * EMB + c0];
            atomicAdd(dst,     vA.x);
            atomicAdd(dst + 1, vB.x);
        }
        if (t0 + 1 < rem) {
            int tok = g_tokens[s0cb + t0 + 1];
            float* dst = &out[((size_t)tok * 4 + m) * EMB + c0];
            atomicAdd(dst,     vA.y);
            atomicAdd(dst + 1, vB.y);
        }
    }
}

__device__ __forceinline__ void consumer(const Params& p, float* __restrict__ out,
                                         int b2, char* smem_raw) {
    // decode: b2 = e*32 + m*8 + kh*4 + tile
    int tile = b2 & 3;
    int kh   = (b2 >> 2) & 1;
    int m    = (b2 >> 3) & 3;
    int e    = b2 >> 5;
    int tid  = threadIdx.x;

    // wait: grouping published
    if (tid == 0) {
        volatile int* f = &g_flags[N_PROD];
        while (!*f) __nanosleep(200);
    }
    __syncthreads();
    __threadfence();

    int s0 = g_start[e];
    int n  = g_start[e + 1] - s0;
    if (n == 0) return;

    // wait: our two hidden-column quarters of (m,e)
    if (tid < 2) {
        volatile int* f = &g_flags[(m * 32 + e) * 4 + 2 * kh + tid];
        while (!*f) __nanosleep(200);
    }
    __syncthreads();
    __threadfence();

    float* hs = (float*)smem_raw;
    int c0 = tile * 256 + tid * 2;
    const float* __restrict__ W2ec = p.W2[m] + (size_t)e * HID * EMB
                                   + (size_t)kh * KC * EMB + c0;
    const float* __restrict__ Hme  = g_H + m * HID + kh * KC;
    float2 init = (kh == 0)
        ? make_float2(p.b2[m][e * EMB + c0]     + p.te[m][c0],
                      p.b2[m][e * EMB + c0 + 1] + p.te[m][c0 + 1])
        : make_float2(0.f, 0.f);

    for (int cb = 0; cb < n; cb += CHT) {
        int rem = min(n - cb, CHT);
        int pairsEven = ((rem + 3) >> 2) << 1; // even ceil(rem/2)
        int s0cb = s0 + cb;
        switch (pairsEven) {
#define CASE(PP) case PP: run_chunk<PP>(hs, W2ec, Hme, init, s0cb, rem, tid, c0, m, out); break;
            CASE(2) CASE(4) CASE(6) CASE(8) CASE(10) CASE(12)
#undef CASE
        }
    }
}

// ---------------------------------------------------------------------------
__global__ void __launch_bounds__(128, 4) k_all(Params p,
                                                const float* __restrict__ state,
                                                const int* __restrict__ ids_raw,
                                                float* __restrict__ out) {
    __shared__ __align__(16) char smem_raw[KC * HSS * 4]; // 28672 B, both paths
    int bid = blockIdx.x;
    if (bid < N_PROD) producer(p, state, ids_raw, bid, smem_raw);
    else              consumer(p, out, bid - N_PROD, smem_raw);
}

// ---------------------------------------------------------------------------
extern "C" void kernel_launch(void* const* d_in, const int* in_sizes, int n_in,
                              void* d_out, int out_size) {
    const float* state = (const float*)d_in[0];
    const int*   ids   = (const int*)d_in[1];

    Params P;
    int base = 2;
    for (int m = 0; m < 4; m++) {
        P.W1[m] = (const float*)d_in[base + 0];
        P.b1[m] = (const float*)d_in[base + 1];
        P.W2[m] = (const float*)d_in[base + 2];
        P.b2[m] = (const float*)d_in[base + 3];
        P.te[m] = (const float*)d_in[base + 4];
        base += 5;
    }
    float* out = (float*)d_out;

    // reset flags + zero output (graph-capturable memset nodes)
    void* flags_ptr = nullptr;
    cudaGetSymbolAddress(&flags_ptr, g_flags);
    cudaMemsetAsync(flags_ptr, 0, sizeof(int) * (N_PROD + 1));
    cudaMemsetAsync(out, 0, (size_t)out_size * sizeof(float));

    k_all<<<N_PROD + N_CONS, 128>>>(P, state, ids, out);
}